// round 6
// baseline (speedup 1.0000x reference)
#include <cuda_runtime.h>
#include <cuda_bf16.h>
#include <cstdint>

#define Bn   128
#define Sn   512
#define Ln   64
#define NPAIRS ((Bn-1)*Sn)       // 65024
#define PPB  128
#define NBLK (NPAIRS/PPB)        // 508
#define NQ   (Bn*Sn)             // 65536
#define EPITCH 132               // est column pitch (floats)

#define LOG2E 1.4426950408889634f
#define LN2f  0.6931471805599453f

__device__ float  g_alpha[Ln];
__device__ double g_score;
__device__ float  gExpT[Ln*Ln];   // [j*64+i] = 2^(T[i][j]*log2e)

__device__ __forceinline__ float ex2f(float x){ float y; asm("ex2.approx.f32 %0, %1;" : "=f"(y) : "f"(x)); return y; }
__device__ __forceinline__ float lg2f_(float x){ float y; asm("lg2.approx.f32 %0, %1;" : "=f"(y) : "f"(x)); return y; }
__device__ __forceinline__ void ffma2(unsigned long long& d, unsigned long long a, unsigned long long b){
    asm("fma.rn.f32x2 %0, %1, %2, %0;" : "+l"(d) : "l"(a), "l"(b));
}
__device__ __forceinline__ unsigned long long pack2(float v){
    unsigned long long r; asm("mov.b64 %0, {%1, %1};" : "=l"(r) : "f"(v)); return r;
}

// ---------------------------------------------------------------------------
// K0: zero accumulators + build expT (transposed).  16 blocks.
// ---------------------------------------------------------------------------
__global__ void initz_kernel(const float* __restrict__ trans){
    int t = threadIdx.x;
    if (blockIdx.x == 0){
        if (t < Ln)  g_alpha[t] = 0.0f;
        if (t == Ln) g_score = 0.0;
    }
    int o = blockIdx.x*256 + t;      // o = j*64 + i
    int i = o & 63, j = o >> 6;
    gExpT[o] = ex2f(trans[i*64 + j] * LOG2E);
}

// ---------------------------------------------------------------------------
// K1: start/end transition score.  One block per batch, int4 counting.
// ---------------------------------------------------------------------------
__global__ __launch_bounds__(128) void score_ends_kernel(
    const int* __restrict__ labels, const int* __restrict__ mask,
    const float* __restrict__ strans, const float* __restrict__ etrans)
{
    int b = blockIdx.x, t = threadIdx.x;
    const int4 m = ((const int4*)(mask + b*Sn))[t];
    int cnt = (m.x!=0) + (m.y!=0) + (m.z!=0) + (m.w!=0);
    #pragma unroll
    for (int o = 16; o; o >>= 1) cnt += __shfl_down_sync(0xffffffffu, cnt, o);
    __shared__ int sc[4];
    if ((t & 31) == 0) sc[t >> 5] = cnt;
    __syncthreads();
    if (t == 0){
        int c = sc[0] + sc[1] + sc[2] + sc[3];
        int end = c - 1; if (end < 0) end = 0;
        const int* lab = labels + b*Sn;
        atomicAdd(&g_score, (double)strans[lab[0]] + (double)etrans[lab[end]]);
    }
}

// ---------------------------------------------------------------------------
// K2: per-step label score, one (b,s) per thread.
// ---------------------------------------------------------------------------
__global__ __launch_bounds__(256) void score_main_kernel(
    const float* __restrict__ emit, const int* __restrict__ labels,
    const int* __restrict__ mask, const float* __restrict__ trans)
{
    int t = threadIdx.x;
    int g = blockIdx.x*256 + t;
    float v = 0.f;
    if (mask[g]){
        int l = labels[g];
        v = emit[(size_t)g*Ln + l];
        if (g & 511) v += trans[labels[g-1]*Ln + l];
    }
    #pragma unroll
    for (int o = 16; o; o >>= 1) v += __shfl_down_sync(0xffffffffu, v, o);
    __shared__ float sp[8];
    if ((t & 31) == 0) sp[t >> 5] = v;
    __syncthreads();
    if (t == 0){
        double tot = 0.0;
        #pragma unroll
        for (int i = 0; i < 8; ++i) tot += (double)sp[i];
        atomicAdd(&g_score, tot);
    }
}

// ---------------------------------------------------------------------------
// K3: alpha.  Per block: 128 pairs.  est column-major [j][p] (pitch 132).
// Inner loop per j: 1 T-LDS.128 + 2 e-LDS.128 + 4 pack + 16 FFMA2 (f32x2).
// ---------------------------------------------------------------------------
__global__ __launch_bounds__(256, 4) void alpha_kernel(
    const float* __restrict__ emit, const int* __restrict__ mask)
{
    __shared__ __align__(16) float sT[Ln*Ln];        // [j*64 + i]
    __shared__ __align__(16) float est[Ln*EPITCH];   // [j*132 + p]
    __shared__ float flags[PPB];

    int t  = threadIdx.x;
    int p0 = blockIdx.x * PPB;

    // expT tile (coalesced, conflict-free)
    {
        const float4* gT4 = (const float4*)gExpT;
        float4* sT4 = (float4*)sT;
        #pragma unroll
        for (int it = 0; it < 4; ++it) sT4[t + it*256] = gT4[t + it*256];
    }
    // emit tile: coalesced float4 read, ex2, transposed scalar STS.
    {
        int p  = t >> 1;                       // 0..127
        int jh = (t & 1) * 32;                 // half-row
        const float4* src = (const float4*)(emit + ((size_t)(p0 + Sn + p))*Ln + jh);
        #pragma unroll
        for (int q = 0; q < 8; ++q){
            float4 v = src[q];
            int j = jh + 4*q;
            est[(j  )*EPITCH + p] = ex2f(v.x * LOG2E);
            est[(j+1)*EPITCH + p] = ex2f(v.y * LOG2E);
            est[(j+2)*EPITCH + p] = ex2f(v.z * LOG2E);
            est[(j+3)*EPITCH + p] = ex2f(v.w * LOG2E);
        }
    }
    if (t < PPB){
        int p = p0 + t;
        int b = 1 + (p >> 9), s = p & 511;
        flags[t] = mask[b*Sn + s] ? 1.0f : 0.0f;
    }
    __syncthreads();

    const int i4 = t & 15;             // i = 4*i4 .. 4*i4+3
    const int pg = t >> 4;             // p = pg*8 .. pg*8+7
    unsigned long long acc[4][4];      // [k][m] packed over p=(2m, 2m+1)
    #pragma unroll
    for (int k = 0; k < 4; ++k)
        #pragma unroll
        for (int m = 0; m < 4; ++m) acc[k][m] = 0ull;

    const float4* pT = (const float4*)(sT) + i4;               // step 16 per j
    const ulonglong2* pE = (const ulonglong2*)(est) + pg;      // step 33 per j

    #pragma unroll 8
    for (int j = 0; j < 64; ++j){
        float4 tv = pT[j*16];
        ulonglong2 ea = pE[j*33];          // pairs (e0,e1),(e2,e3)
        ulonglong2 eb = pE[j*33 + 1];      // pairs (e4,e5),(e6,e7)
        unsigned long long tp[4] = {pack2(tv.x), pack2(tv.y), pack2(tv.z), pack2(tv.w)};
        unsigned long long ep[4] = {ea.x, ea.y, eb.x, eb.y};
        #pragma unroll
        for (int k = 0; k < 4; ++k){
            ffma2(acc[k][0], tp[k], ep[0]);
            ffma2(acc[k][1], tp[k], ep[1]);
            ffma2(acc[k][2], tp[k], ep[2]);
            ffma2(acc[k][3], tp[k], ep[3]);
        }
    }

    // unpack + log2 + masked accumulate
    float csum[4] = {0.f, 0.f, 0.f, 0.f};
    #pragma unroll
    for (int m = 0; m < 4; ++m){
        float f0 = flags[(pg << 3) + 2*m];
        float f1 = flags[(pg << 3) + 2*m + 1];
        #pragma unroll
        for (int k = 0; k < 4; ++k){
            float lo = __uint_as_float((unsigned)(acc[k][m] & 0xffffffffull));
            float hi = __uint_as_float((unsigned)(acc[k][m] >> 32));
            csum[k] += f0 * lg2f_(lo) + f1 * lg2f_(hi);
        }
    }

    __syncthreads();
    float* red = est;                  // reuse: red[pg*64 + i]
    #pragma unroll
    for (int k = 0; k < 4; ++k) red[pg*64 + (i4 << 2) + k] = csum[k];
    __syncthreads();

    if (t < Ln){
        float s = 0.f;
        #pragma unroll
        for (int g = 0; g < 16; ++g) s += red[g*64 + t];
        atomicAdd(&g_alpha[t], s * LN2f);
    }
}

// ---------------------------------------------------------------------------
// K4: finalize (parallel float LSE).
// ---------------------------------------------------------------------------
__global__ void fin_kernel(const float* __restrict__ emit, float* __restrict__ out){
    int t = threadIdx.x;                       // 64 threads
    float a = g_alpha[t] + emit[t];            // + emit[0,0,:]
    float m = a;
    #pragma unroll
    for (int o = 16; o; o >>= 1) m = fmaxf(m, __shfl_xor_sync(0xffffffffu, m, o));
    __shared__ float sm[2];
    if ((t & 31) == 0) sm[t >> 5] = m;
    __syncthreads();
    m = fmaxf(sm[0], sm[1]);
    float e = ex2f((a - m) * LOG2E);
    #pragma unroll
    for (int o = 16; o; o >>= 1) e += __shfl_xor_sync(0xffffffffu, e, o);
    __shared__ float se[2];
    if ((t & 31) == 0) se[t >> 5] = e;
    __syncthreads();
    if (t == 0){
        double logZ = (double)m + (double)(LN2f * lg2f_(se[0] + se[1]));
        out[0] = (float)((logZ - g_score) / (double)Bn);
    }
}

// ---------------------------------------------------------------------------
extern "C" void kernel_launch(void* const* d_in, const int* in_sizes, int n_in,
                              void* d_out, int out_size)
{
    const float* emit   = (const float*)d_in[0];
    const int*   labels = (const int*)d_in[1];
    const int*   mask   = (const int*)d_in[2];
    const float* trans  = (const float*)d_in[3];
    const float* strans = (const float*)d_in[4];
    const float* etrans = (const float*)d_in[5];
    float* out = (float*)d_out;

    initz_kernel<<<16, 256>>>(trans);
    score_ends_kernel<<<Bn, 128>>>(labels, mask, strans, etrans);
    score_main_kernel<<<NQ/256, 256>>>(emit, labels, mask, trans);
    alpha_kernel<<<NBLK, 256>>>(emit, mask);     // launch index 3 (ncu slot)
    fin_kernel<<<1, 64>>>(emit, out);
}

// round 7
// speedup vs baseline: 1.1158x; 1.1158x over previous
#include <cuda_runtime.h>
#include <cuda_bf16.h>
#include <cstdint>

#define Bn   128
#define Sn   512
#define Ln   64
#define NPAIRS ((Bn-1)*Sn)       // 65024
#define PPB  128
#define NBLK (NPAIRS/PPB)        // 508
#define NQ   (Bn*Sn)             // 65536
#define EPITCH 132               // est column pitch (floats)

#define LOG2E 1.4426950408889634f
#define LN2f  0.6931471805599453f

__device__ float    g_alpha[Ln];
__device__ double   g_score;
__device__ unsigned g_done;
__device__ float    gExpT[Ln*Ln];   // [j*64+i] = 2^(T[i][j]*log2e)

__device__ __forceinline__ float ex2f(float x){ float y; asm("ex2.approx.f32 %0, %1;" : "=f"(y) : "f"(x)); return y; }
__device__ __forceinline__ float lg2f_(float x){ float y; asm("lg2.approx.f32 %0, %1;" : "=f"(y) : "f"(x)); return y; }
__device__ __forceinline__ void ffma2(unsigned long long& d, unsigned long long a, unsigned long long b){
    asm("fma.rn.f32x2 %0, %1, %2, %0;" : "+l"(d) : "l"(a), "l"(b));
}
__device__ __forceinline__ unsigned long long pack2(float v){
    unsigned long long r; asm("mov.b64 %0, {%1, %1};" : "=l"(r) : "f"(v)); return r;
}

// ---------------------------------------------------------------------------
// K0: zero accumulators + done-counter, build expT (transposed).  16 blocks.
// ---------------------------------------------------------------------------
__global__ void initz_kernel(const float* __restrict__ trans){
    int t = threadIdx.x;
    if (blockIdx.x == 0){
        if (t < Ln)   g_alpha[t] = 0.0f;
        if (t == Ln)  g_score = 0.0;
        if (t == Ln+1) g_done = 0u;
    }
    int o = blockIdx.x*256 + t;      // o = j*64 + i
    int i = o & 63, j = o >> 6;
    gExpT[o] = ex2f(trans[i*64 + j] * LOG2E);
}

// ---------------------------------------------------------------------------
// K1: mega kernel.  Per block: 128 (b,s) pairs of alpha work, plus folded
//     label-score gathers, ends-score (blocks<128), and last-block finalize.
// ---------------------------------------------------------------------------
__global__ __launch_bounds__(256, 4) void mega_kernel(
    const float* __restrict__ emit,  const int* __restrict__ labels,
    const int*   __restrict__ mask,  const float* __restrict__ trans,
    const float* __restrict__ strans,const float* __restrict__ etrans,
    float* __restrict__ out)
{
    __shared__ __align__(16) float sT[Ln*Ln];        // [j*64 + i]
    __shared__ __align__(16) float est[Ln*EPITCH];   // [j*132 + p]
    __shared__ float flags[PPB];
    __shared__ float ssc[8];        // per-warp score partials
    __shared__ int   scnt[4];       // ends mask count partials
    __shared__ unsigned slast;

    int t  = threadIdx.x;
    int bx = blockIdx.x;
    int p0 = bx * PPB;

    // ---- prologue: expT tile (coalesced, conflict-free) ----
    {
        const float4* gT4 = (const float4*)gExpT;
        float4* sT4 = (float4*)sT;
        #pragma unroll
        for (int it = 0; it < 4; ++it) sT4[t + it*256] = gT4[t + it*256];
    }
    // ---- emit tile: coalesced float4 read, ex2, transposed scalar STS ----
    {
        int p  = t >> 1;                       // 0..127
        int jh = (t & 1) * 32;                 // half-row
        const float4* src = (const float4*)(emit + ((size_t)(p0 + Sn + p))*Ln + jh);
        #pragma unroll
        for (int q = 0; q < 8; ++q){
            float4 v = src[q];
            int j = jh + 4*q;
            est[(j  )*EPITCH + p] = ex2f(v.x * LOG2E);
            est[(j+1)*EPITCH + p] = ex2f(v.y * LOG2E);
            est[(j+2)*EPITCH + p] = ex2f(v.z * LOG2E);
            est[(j+3)*EPITCH + p] = ex2f(v.w * LOG2E);
        }
    }
    if (t < PPB){
        int p = p0 + t;
        int b = 1 + (p >> 9), s = p & 511;
        flags[t] = mask[b*Sn + s] ? 1.0f : 0.0f;
    }

    // ---- folded per-step label score ----
    {
        float v = 0.f;
        int g = -1;
        if (t < PPB)            g = p0 + Sn + t;           // this block's pairs
        else if (bx < 4)        g = bx*128 + (t - 128);    // b=0 region (g in [0,512))
        if (g >= 0 && mask[g]){
            int l = labels[g];
            v = emit[(size_t)g*Ln + l];
            if (g & 511) v += trans[labels[g-1]*Ln + l];
        }
        #pragma unroll
        for (int o = 16; o; o >>= 1) v += __shfl_down_sync(0xffffffffu, v, o);
        if ((t & 31) == 0) ssc[t >> 5] = v;
    }
    // ---- folded ends score (blocks 0..127, one batch each) ----
    if (bx < Bn && t >= 128){
        int tt = t - 128;                                  // 0..127
        const int4 m = ((const int4*)(mask + bx*Sn))[tt];
        int cnt = (m.x!=0) + (m.y!=0) + (m.z!=0) + (m.w!=0);
        #pragma unroll
        for (int o = 16; o; o >>= 1) cnt += __shfl_down_sync(0xffffffffu, cnt, o);
        if ((tt & 31) == 0) scnt[tt >> 5] = cnt;
    }
    __syncthreads();

    if (t == 0){
        double tot = 0.0;
        #pragma unroll
        for (int i = 0; i < 8; ++i) tot += (double)ssc[i];
        if (bx < Bn){
            int c = scnt[0] + scnt[1] + scnt[2] + scnt[3];
            int end = c - 1; if (end < 0) end = 0;
            const int* lab = labels + bx*Sn;
            tot += (double)strans[lab[0]] + (double)etrans[lab[end]];
        }
        atomicAdd(&g_score, tot);
    }

    // ---- mainloop: packed f32x2 FFMA ----
    const int i4 = t & 15;             // i = 4*i4 .. 4*i4+3
    const int pg = t >> 4;             // p = pg*8 .. pg*8+7
    unsigned long long acc[4][4];
    #pragma unroll
    for (int k = 0; k < 4; ++k)
        #pragma unroll
        for (int m = 0; m < 4; ++m) acc[k][m] = 0ull;

    const float4*     pT = (const float4*)(sT) + i4;           // step 16/j
    const ulonglong2* pE = (const ulonglong2*)(est) + pg*2;    // step 33/j (FIXED: pg*2)

    #pragma unroll 8
    for (int j = 0; j < 64; ++j){
        float4 tv = pT[j*16];
        ulonglong2 ea = pE[j*33];          // pairs (e0,e1),(e2,e3)
        ulonglong2 eb = pE[j*33 + 1];      // pairs (e4,e5),(e6,e7)
        unsigned long long tp[4] = {pack2(tv.x), pack2(tv.y), pack2(tv.z), pack2(tv.w)};
        unsigned long long ep[4] = {ea.x, ea.y, eb.x, eb.y};
        #pragma unroll
        for (int k = 0; k < 4; ++k){
            ffma2(acc[k][0], tp[k], ep[0]);
            ffma2(acc[k][1], tp[k], ep[1]);
            ffma2(acc[k][2], tp[k], ep[2]);
            ffma2(acc[k][3], tp[k], ep[3]);
        }
    }

    // ---- unpack + log2 + masked accumulate ----
    float csum[4] = {0.f, 0.f, 0.f, 0.f};
    #pragma unroll
    for (int m = 0; m < 4; ++m){
        float f0 = flags[(pg << 3) + 2*m];
        float f1 = flags[(pg << 3) + 2*m + 1];
        #pragma unroll
        for (int k = 0; k < 4; ++k){
            float lo = __uint_as_float((unsigned)(acc[k][m] & 0xffffffffull));
            float hi = __uint_as_float((unsigned)(acc[k][m] >> 32));
            csum[k] += f0 * lg2f_(lo) + f1 * lg2f_(hi);
        }
    }

    __syncthreads();
    float* red = est;                  // reuse est: red[pg*64 + i]
    #pragma unroll
    for (int k = 0; k < 4; ++k) red[pg*64 + (i4 << 2) + k] = csum[k];
    __syncthreads();

    if (t < Ln){
        float s = 0.f;
        #pragma unroll
        for (int g = 0; g < 16; ++g) s += red[g*64 + t];
        atomicAdd(&g_alpha[t], s * LN2f);
    }

    // ---- last-block finalize ----
    __threadfence();
    if (t == 0){
        unsigned prev = atomicAdd(&g_done, 1u);
        slast = (prev == NBLK - 1) ? 1u : 0u;
    }
    __syncthreads();
    if (slast && t < Ln){
        float a = g_alpha[t] + emit[t];        // + emit[0,0,:]
        float m = a;
        #pragma unroll
        for (int o = 16; o; o >>= 1) m = fmaxf(m, __shfl_xor_sync(0xffffffffu, m, o));
        float* sm = red;                       // reuse smem
        if ((t & 31) == 0) sm[t >> 5] = m;
        __syncwarp();
        // cross-warp: both warps read both maxima via smem (tiny spin-free handshake)
        __syncthreads();
        m = fmaxf(sm[0], sm[1]);
        float e = ex2f((a - m) * LOG2E);
        #pragma unroll
        for (int o = 16; o; o >>= 1) e += __shfl_xor_sync(0xffffffffu, e, o);
        if ((t & 31) == 0) sm[2 + (t >> 5)] = e;
        __syncthreads();
        if (t == 0){
            double logZ = (double)m + (double)(LN2f * lg2f_(sm[2] + sm[3]));
            out[0] = (float)((logZ - g_score) / (double)Bn);
        }
    } else if (slast == 0 && false) {}
}

// ---------------------------------------------------------------------------
extern "C" void kernel_launch(void* const* d_in, const int* in_sizes, int n_in,
                              void* d_out, int out_size)
{
    const float* emit   = (const float*)d_in[0];
    const int*   labels = (const int*)d_in[1];
    const int*   mask   = (const int*)d_in[2];
    const float* trans  = (const float*)d_in[3];
    const float* strans = (const float*)d_in[4];
    const float* etrans = (const float*)d_in[5];
    float* out = (float*)d_out;

    initz_kernel<<<16, 256>>>(trans);
    mega_kernel<<<NBLK, 256>>>(emit, labels, mask, trans, strans, etrans, out);
}

// round 9
// speedup vs baseline: 1.1497x; 1.0304x over previous
#include <cuda_runtime.h>
#include <cuda_bf16.h>
#include <cstdint>

#define Bn   128
#define Sn   512
#define Ln   64
#define NPAIRS ((Bn-1)*Sn)       // 65024
#define PPB  128
#define NBLK (NPAIRS/PPB)        // 508
#define NQ   (Bn*Sn)             // 65536
#define EPITCH 132               // est column pitch (floats)

#define LOG2E 1.4426950408889634f
#define LN2f  0.6931471805599453f

__device__ float    g_alpha[Ln];
__device__ double   g_score;
__device__ unsigned g_done;
__device__ float    gExpT[Ln*Ln];   // [j*64+i] = 2^(T[i][j]*log2e)

__device__ __forceinline__ float ex2f(float x){ float y; asm("ex2.approx.f32 %0, %1;" : "=f"(y) : "f"(x)); return y; }
__device__ __forceinline__ float lg2f_(float x){ float y; asm("lg2.approx.f32 %0, %1;" : "=f"(y) : "f"(x)); return y; }
__device__ __forceinline__ void ffma2(unsigned long long& d, unsigned long long a, unsigned long long b){
    asm("fma.rn.f32x2 %0, %1, %2, %0;" : "+l"(d) : "l"(a), "l"(b));
}
__device__ __forceinline__ unsigned long long pack2(float v){
    unsigned long long r; asm("mov.b64 %0, {%1, %1};" : "=l"(r) : "f"(v)); return r;
}

// ---------------------------------------------------------------------------
// K0: zero accumulators + done-counter, build expT (transposed).  16 blocks.
// ---------------------------------------------------------------------------
__global__ void initz_kernel(const float* __restrict__ trans){
    int t = threadIdx.x;
    if (blockIdx.x == 0){
        if (t < Ln)    g_alpha[t] = 0.0f;
        if (t == Ln)   g_score = 0.0;
        if (t == Ln+1) g_done = 0u;
    }
    int o = blockIdx.x*256 + t;      // o = j*64 + i
    int i = o & 63, j = o >> 6;
    gExpT[o] = ex2f(trans[i*64 + j] * LOG2E);
}

// ---------------------------------------------------------------------------
// K1: mega kernel.  Per block: 128 (b,s) pairs of alpha work, plus folded
//     label-score gathers, ends-score (blocks<128), and last-block finalize.
// ---------------------------------------------------------------------------
__global__ __launch_bounds__(256, 4) void mega_kernel(
    const float* __restrict__ emit,  const int* __restrict__ labels,
    const int*   __restrict__ mask,  const float* __restrict__ trans,
    const float* __restrict__ strans,const float* __restrict__ etrans,
    float* __restrict__ out)
{
    __shared__ __align__(16) float sT[Ln*Ln];        // [j*64 + i]
    __shared__ __align__(16) float est[Ln*EPITCH];   // [j*132 + p]
    __shared__ float flags[PPB];
    __shared__ float ssc[8];        // per-warp score partials
    __shared__ int   scnt[4];       // ends mask count partials
    __shared__ unsigned slast;

    int t  = threadIdx.x;
    int bx = blockIdx.x;
    int p0 = bx * PPB;

    // ---- emit tile: LANE-LINEAR coalesced float4 LDG, ex2, transposed STS ----
    {
        const float4* e4 = (const float4*)(emit + (size_t)(p0 + Sn)*Ln);
        #pragma unroll
        for (int it = 0; it < 8; ++it){
            int v = t + it*256;            // 0..2047 linear float4 index
            float4 x = e4[v];
            int p  = v >> 4;               // row (pair)
            int j0 = (v & 15) * 4;         // 4 consecutive j
            est[(j0  )*EPITCH + p] = ex2f(x.x * LOG2E);
            est[(j0+1)*EPITCH + p] = ex2f(x.y * LOG2E);
            est[(j0+2)*EPITCH + p] = ex2f(x.z * LOG2E);
            est[(j0+3)*EPITCH + p] = ex2f(x.w * LOG2E);
        }
    }
    // ---- prologue: expT tile (coalesced, conflict-free) ----
    {
        const float4* gT4 = (const float4*)gExpT;
        float4* sT4 = (float4*)sT;
        #pragma unroll
        for (int it = 0; it < 4; ++it) sT4[t + it*256] = gT4[t + it*256];
    }
    if (t < PPB){
        int p = p0 + t;
        int b = 1 + (p >> 9), s = p & 511;
        flags[t] = mask[b*Sn + s] ? 1.0f : 0.0f;
    }

    // ---- folded per-step label score ----
    {
        float v = 0.f;
        int g = -1;
        if (t < PPB)            g = p0 + Sn + t;           // this block's pairs
        else if (bx < 4)        g = bx*128 + (t - 128);    // b=0 region (g in [0,512))
        if (g >= 0 && mask[g]){
            int l = labels[g];
            v = emit[(size_t)g*Ln + l];
            if (g & 511) v += trans[labels[g-1]*Ln + l];
        }
        #pragma unroll
        for (int o = 16; o; o >>= 1) v += __shfl_down_sync(0xffffffffu, v, o);
        if ((t & 31) == 0) ssc[t >> 5] = v;
    }
    // ---- folded ends score (blocks 0..127, one batch each) ----
    if (bx < Bn && t >= 128){
        int tt = t - 128;                                  // 0..127
        const int4 m = ((const int4*)(mask + bx*Sn))[tt];
        int cnt = (m.x!=0) + (m.y!=0) + (m.z!=0) + (m.w!=0);
        #pragma unroll
        for (int o = 16; o; o >>= 1) cnt += __shfl_down_sync(0xffffffffu, cnt, o);
        if ((tt & 31) == 0) scnt[tt >> 5] = cnt;
    }
    __syncthreads();

    if (t == 0){
        double tot = 0.0;
        #pragma unroll
        for (int i = 0; i < 8; ++i) tot += (double)ssc[i];
        if (bx < Bn){
            int c = scnt[0] + scnt[1] + scnt[2] + scnt[3];
            int end = c - 1; if (end < 0) end = 0;
            const int* lab = labels + bx*Sn;
            tot += (double)strans[lab[0]] + (double)etrans[lab[end]];
        }
        atomicAdd(&g_score, tot);
    }

    // ---- mainloop: packed f32x2 FFMA ----
    const int i4 = t & 15;             // i = 4*i4 .. 4*i4+3
    const int pg = t >> 4;             // p = pg*8 .. pg*8+7
    unsigned long long acc[4][4];
    #pragma unroll
    for (int k = 0; k < 4; ++k)
        #pragma unroll
        for (int m = 0; m < 4; ++m) acc[k][m] = 0ull;

    const float4*     pT = (const float4*)(sT) + i4;           // step 16/j
    const ulonglong2* pE = (const ulonglong2*)(est) + pg*2;    // step 33/j

    #pragma unroll 8
    for (int j = 0; j < 64; ++j){
        float4 tv = pT[j*16];
        ulonglong2 ea = pE[j*33];          // pairs (e0,e1),(e2,e3)
        ulonglong2 eb = pE[j*33 + 1];      // pairs (e4,e5),(e6,e7)
        unsigned long long tp[4] = {pack2(tv.x), pack2(tv.y), pack2(tv.z), pack2(tv.w)};
        unsigned long long ep[4] = {ea.x, ea.y, eb.x, eb.y};
        #pragma unroll
        for (int k = 0; k < 4; ++k){
            ffma2(acc[k][0], tp[k], ep[0]);
            ffma2(acc[k][1], tp[k], ep[1]);
            ffma2(acc[k][2], tp[k], ep[2]);
            ffma2(acc[k][3], tp[k], ep[3]);
        }
    }

    // ---- unpack + log2 + masked accumulate ----
    float csum[4] = {0.f, 0.f, 0.f, 0.f};
    #pragma unroll
    for (int m = 0; m < 4; ++m){
        float f0 = flags[(pg << 3) + 2*m];
        float f1 = flags[(pg << 3) + 2*m + 1];
        #pragma unroll
        for (int k = 0; k < 4; ++k){
            float lo = __uint_as_float((unsigned)(acc[k][m] & 0xffffffffull));
            float hi = __uint_as_float((unsigned)(acc[k][m] >> 32));
            csum[k] += f0 * lg2f_(lo) + f1 * lg2f_(hi);
        }
    }

    __syncthreads();
    float* red = est;                  // reuse est: red[pg*64 + i]
    #pragma unroll
    for (int k = 0; k < 4; ++k) red[pg*64 + (i4 << 2) + k] = csum[k];
    __syncthreads();

    if (t < Ln){
        float s = 0.f;
        #pragma unroll
        for (int g = 0; g < 16; ++g) s += red[g*64 + t];
        atomicAdd(&g_alpha[t], s * LN2f);
    }

    // ---- last-block finalize ----
    __threadfence();
    if (t == 0){
        unsigned prev = atomicAdd(&g_done, 1u);
        slast = (prev == NBLK - 1) ? 1u : 0u;
    }
    __syncthreads();
    if (slast && t < Ln){
        float a = g_alpha[t] + emit[t];        // + emit[0,0,:]
        float m = a;
        #pragma unroll
        for (int o = 16; o; o >>= 1) m = fmaxf(m, __shfl_xor_sync(0xffffffffu, m, o));
        float* sm = red;                       // reuse smem
        if ((t & 31) == 0) sm[t >> 5] = m;
        __syncwarp();
        __syncthreads();
        m = fmaxf(sm[0], sm[1]);
        float e = ex2f((a - m) * LOG2E);
        #pragma unroll
        for (int o = 16; o; o >>= 1) e += __shfl_xor_sync(0xffffffffu, e, o);
        if ((t & 31) == 0) sm[2 + (t >> 5)] = e;
        __syncthreads();
        if (t == 0){
            double logZ = (double)m + (double)(LN2f * lg2f_(sm[2] + sm[3]));
            out[0] = (float)((logZ - g_score) / (double)Bn);
        }
    }
}

// ---------------------------------------------------------------------------
extern "C" void kernel_launch(void* const* d_in, const int* in_sizes, int n_in,
                              void* d_out, int out_size)
{
    const float* emit   = (const float*)d_in[0];
    const int*   labels = (const int*)d_in[1];
    const int*   mask   = (const int*)d_in[2];
    const float* trans  = (const float*)d_in[3];
    const float* strans = (const float*)d_in[4];
    const float* etrans = (const float*)d_in[5];
    float* out = (float*)d_out;

    initz_kernel<<<16, 256>>>(trans);
    mega_kernel<<<NBLK, 256>>>(emit, labels, mask, trans, strans, etrans, out);
}

// round 10
// speedup vs baseline: 1.2396x; 1.0782x over previous
#include <cuda_runtime.h>
#include <cuda_bf16.h>
#include <cstdint>

#define Bn   128
#define Sn   512
#define Ln   64
#define NPAIRS ((Bn-1)*Sn)       // 65024
#define PPB  128
#define NBLK (NPAIRS/PPB)        // 508
#define EPITCH 132               // est column pitch (floats)

#define LOG2E 1.4426950408889634f
#define LN2f  0.6931471805599453f

// Zero-initialized at module load; finalizer block resets them after use so
// every graph replay starts from the same state.
__device__ float    g_alpha[Ln];
__device__ double   g_score;
__device__ unsigned g_done;

__device__ __forceinline__ float ex2f(float x){ float y; asm("ex2.approx.f32 %0, %1;" : "=f"(y) : "f"(x)); return y; }
__device__ __forceinline__ float lg2f_(float x){ float y; asm("lg2.approx.f32 %0, %1;" : "=f"(y) : "f"(x)); return y; }
__device__ __forceinline__ void ffma2(unsigned long long& d, unsigned long long a, unsigned long long b){
    asm("fma.rn.f32x2 %0, %1, %2, %0;" : "+l"(d) : "l"(a), "l"(b));
}
__device__ __forceinline__ unsigned long long pack2(float v){
    unsigned long long r; asm("mov.b64 %0, {%1, %1};" : "=l"(r) : "f"(v)); return r;
}

// ---------------------------------------------------------------------------
// Mega kernel (single launch).  Per block: 128 (b,s) pairs of alpha work,
// folded label-score gathers, ends-score (blocks<128), last-block finalize
// with self-resetting accumulators.
// ---------------------------------------------------------------------------
__global__ __launch_bounds__(256, 4) void mega_kernel(
    const float* __restrict__ emit,  const int* __restrict__ labels,
    const int*   __restrict__ mask,  const float* __restrict__ trans,
    const float* __restrict__ strans,const float* __restrict__ etrans,
    float* __restrict__ out)
{
    __shared__ __align__(16) float sT[Ln*Ln];        // swizzled [j][i] expT
    __shared__ __align__(16) float est[Ln*EPITCH];   // [j*132 + p]
    __shared__ float flags[PPB];
    __shared__ float ssc[8];
    __shared__ int   scnt[4];
    __shared__ unsigned slast;

    int t  = threadIdx.x;
    int bx = blockIdx.x;
    int p0 = bx * PPB;

    // ======== front-issue ALL long-latency loads ========
    // emit tile (lane-linear float4)
    float4 ex[8];
    {
        const float4* e4 = (const float4*)(emit + (size_t)(p0 + Sn)*Ln);
        #pragma unroll
        for (int it = 0; it < 8; ++it) ex[it] = e4[t + it*256];
    }
    // scattered score gathers (unconditional; masked at consume time)
    int g = -1;
    if (t < PPB)      g = p0 + Sn + t;
    else if (bx < 4)  g = bx*128 + (t - 128);
    int gg = (g >= 0) ? g : 0;
    int l    = labels[gg];
    int lp   = labels[(gg > 0) ? gg - 1 : 0];
    float em_v = emit[(size_t)gg*Ln + l];
    float tr_v = trans[lp*Ln + l];
    int   mk_v = mask[gg];
    // ends-score mask row (coalesced int4)
    int4 mker = make_int4(0,0,0,0);
    if (bx < Bn && t >= 128) mker = ((const int4*)(mask + bx*Sn))[t - 128];

    // ======== build expT tile in-block (coalesced trans LDG, swizzled STS) ========
    // sT float4-index for (j, i4): j*16 + (i4 ^ (j & 15))
    #pragma unroll
    for (int it = 0; it < 16; ++it){
        int o = t + it*256;            // 0..4095
        int i = o >> 6, j = o & 63;
        float v = ex2f(trans[i*64 + j] * LOG2E);
        sT[(j*16 + ((i >> 2) ^ (j & 15)))*4 + (i & 3)] = v;
    }

    // ======== est fill (ex2 + transposed STS) ========
    #pragma unroll
    for (int it = 0; it < 8; ++it){
        int v = t + it*256;
        int p  = v >> 4;
        int j0 = (v & 15) * 4;
        est[(j0  )*EPITCH + p] = ex2f(ex[it].x * LOG2E);
        est[(j0+1)*EPITCH + p] = ex2f(ex[it].y * LOG2E);
        est[(j0+2)*EPITCH + p] = ex2f(ex[it].z * LOG2E);
        est[(j0+3)*EPITCH + p] = ex2f(ex[it].w * LOG2E);
    }
    if (t < PPB) flags[t] = mk_v ? 1.0f : 0.0f;

    // ======== consume score gathers (latency already covered) ========
    {
        float v = 0.f;
        if (g >= 0 && mk_v){
            v = em_v;
            if (g & 511) v += tr_v;
        }
        #pragma unroll
        for (int o = 16; o; o >>= 1) v += __shfl_down_sync(0xffffffffu, v, o);
        if ((t & 31) == 0) ssc[t >> 5] = v;
    }
    if (bx < Bn && t >= 128){
        int tt = t - 128;
        int cnt = (mker.x!=0) + (mker.y!=0) + (mker.z!=0) + (mker.w!=0);
        #pragma unroll
        for (int o = 16; o; o >>= 1) cnt += __shfl_down_sync(0xffffffffu, cnt, o);
        if ((tt & 31) == 0) scnt[tt >> 5] = cnt;
    }
    __syncthreads();

    if (t == 0){
        double tot = 0.0;
        #pragma unroll
        for (int i = 0; i < 8; ++i) tot += (double)ssc[i];
        if (bx < Bn){
            int c = scnt[0] + scnt[1] + scnt[2] + scnt[3];
            int end = c - 1; if (end < 0) end = 0;
            const int* lab = labels + bx*Sn;
            tot += (double)strans[lab[0]] + (double)etrans[lab[end]];
        }
        atomicAdd(&g_score, tot);
    }

    // ======== mainloop: packed f32x2 FFMA ========
    const int i4 = t & 15;
    const int pg = t >> 4;
    unsigned long long acc[4][4];
    #pragma unroll
    for (int k = 0; k < 4; ++k)
        #pragma unroll
        for (int m = 0; m < 4; ++m) acc[k][m] = 0ull;

    const float4*     sT4 = (const float4*)sT;
    const ulonglong2* pE  = (const ulonglong2*)(est) + pg*2;   // step 33/j

    #pragma unroll 8
    for (int j = 0; j < 64; ++j){
        float4 tv = sT4[j*16 + (i4 ^ (j & 15))];
        ulonglong2 ea = pE[j*33];
        ulonglong2 eb = pE[j*33 + 1];
        unsigned long long tp[4] = {pack2(tv.x), pack2(tv.y), pack2(tv.z), pack2(tv.w)};
        unsigned long long ep[4] = {ea.x, ea.y, eb.x, eb.y};
        #pragma unroll
        for (int k = 0; k < 4; ++k){
            ffma2(acc[k][0], tp[k], ep[0]);
            ffma2(acc[k][1], tp[k], ep[1]);
            ffma2(acc[k][2], tp[k], ep[2]);
            ffma2(acc[k][3], tp[k], ep[3]);
        }
    }

    // ======== unpack + log2 + masked accumulate ========
    float csum[4] = {0.f, 0.f, 0.f, 0.f};
    #pragma unroll
    for (int m = 0; m < 4; ++m){
        float f0 = flags[(pg << 3) + 2*m];
        float f1 = flags[(pg << 3) + 2*m + 1];
        #pragma unroll
        for (int k = 0; k < 4; ++k){
            float lo = __uint_as_float((unsigned)(acc[k][m] & 0xffffffffull));
            float hi = __uint_as_float((unsigned)(acc[k][m] >> 32));
            csum[k] += f0 * lg2f_(lo) + f1 * lg2f_(hi);
        }
    }

    __syncthreads();
    float* red = est;                  // reuse est
    #pragma unroll
    for (int k = 0; k < 4; ++k) red[pg*64 + (i4 << 2) + k] = csum[k];
    __syncthreads();

    if (t < Ln){
        float s = 0.f;
        #pragma unroll
        for (int gi = 0; gi < 16; ++gi) s += red[gi*64 + t];
        atomicAdd(&g_alpha[t], s * LN2f);
    }

    // ======== last-block finalize + state reset ========
    __threadfence();
    if (t == 0){
        unsigned prev = atomicAdd(&g_done, 1u);
        slast = (prev == NBLK - 1) ? 1u : 0u;
    }
    __syncthreads();
    if (slast){
        float a = -1e30f;
        if (t < Ln) a = g_alpha[t] + emit[t];          // + emit[0,0,:]
        float m = a;
        #pragma unroll
        for (int o = 16; o; o >>= 1) m = fmaxf(m, __shfl_xor_sync(0xffffffffu, m, o));
        if ((t & 31) == 0) red[t >> 5] = m;
        __syncthreads();
        m = red[0];
        #pragma unroll
        for (int i = 1; i < 8; ++i) m = fmaxf(m, red[i]);
        float e = (t < Ln) ? ex2f((a - m) * LOG2E) : 0.f;
        #pragma unroll
        for (int o = 16; o; o >>= 1) e += __shfl_xor_sync(0xffffffffu, e, o);
        if ((t & 31) == 0) red[8 + (t >> 5)] = e;
        __syncthreads();
        if (t == 0){
            float es = 0.f;
            #pragma unroll
            for (int i = 0; i < 8; ++i) es += red[8 + i];
            double logZ = (double)m + (double)(LN2f * lg2f_(es));
            out[0] = (float)((logZ - g_score) / (double)Bn);
        }
        __syncthreads();                // all reads of g_alpha/g_score done
        // reset device state for the next replay
        if (t < Ln)  g_alpha[t] = 0.0f;
        if (t == 0){ g_score = 0.0; g_done = 0u; }
    }
}

// ---------------------------------------------------------------------------
extern "C" void kernel_launch(void* const* d_in, const int* in_sizes, int n_in,
                              void* d_out, int out_size)
{
    const float* emit   = (const float*)d_in[0];
    const int*   labels = (const int*)d_in[1];
    const int*   mask   = (const int*)d_in[2];
    const float* trans  = (const float*)d_in[3];
    const float* strans = (const float*)d_in[4];
    const float* etrans = (const float*)d_in[5];
    float* out = (float*)d_out;

    mega_kernel<<<NBLK, 256>>>(emit, labels, mask, trans, strans, etrans, out);
}